// round 1
// baseline (speedup 1.0000x reference)
#include <cuda_runtime.h>

// SpatialTransformer: out[b,c,d,h,w] = trilinear_sample(src[b,c], (w,h,d)+flow[b,:,d,h,w])
// align_corners=True normalization cancels exactly; padding_mode='zeros'.

#define Dz 160
#define Hy 192
#define Wx 160
#define Bn 2
#define Cn 2
#define HW (Hy * Wx)            // 30720
#define DHW (Dz * Hy * Wx)      // 4915200

__global__ __launch_bounds__(256) void warp3d_kernel(
    const float* __restrict__ src,
    const float* __restrict__ flow,
    float* __restrict__ out)
{
    int idx = blockIdx.x * blockDim.x + threadIdx.x;
    if (idx >= Bn * DHW) return;

    int b = idx / DHW;
    int s = idx - b * DHW;
    int w = s % Wx;
    int t = s / Wx;
    int h = t % Hy;
    int d = t / Hy;

    const float* fb = flow + (size_t)b * 3 * DHW;
    float x = (float)w + __ldg(fb + s);
    float y = (float)h + __ldg(fb + s + DHW);
    float z = (float)d + __ldg(fb + s + 2 * DHW);

    float x0f = floorf(x), y0f = floorf(y), z0f = floorf(z);
    float fx = x - x0f, fy = y - y0f, fz = z - z0f;
    int x0 = (int)x0f, y0 = (int)y0f, z0 = (int)z0f;
    int x1 = x0 + 1, y1 = y0 + 1, z1 = z0 + 1;

    // Per-axis weights, zeroed when that corner coordinate is out of bounds.
    float wx0 = (x0 >= 0 && x0 < Wx) ? (1.0f - fx) : 0.0f;
    float wx1 = (x1 >= 0 && x1 < Wx) ? fx          : 0.0f;
    float wy0 = (y0 >= 0 && y0 < Hy) ? (1.0f - fy) : 0.0f;
    float wy1 = (y1 >= 0 && y1 < Hy) ? fy          : 0.0f;
    float wz0 = (z0 >= 0 && z0 < Dz) ? (1.0f - fz) : 0.0f;
    float wz1 = (z1 >= 0 && z1 < Dz) ? fz          : 0.0f;

    // Clamped indices (safe even when weight is zero).
    int x0c = min(max(x0, 0), Wx - 1);
    int x1c = min(max(x1, 0), Wx - 1);
    int y0c = min(max(y0, 0), Hy - 1);
    int y1c = min(max(y1, 0), Hy - 1);
    int z0c = min(max(z0, 0), Dz - 1);
    int z1c = min(max(z1, 0), Dz - 1);

    int zy00 = z0c * HW + y0c * Wx;
    int zy01 = z0c * HW + y1c * Wx;
    int zy10 = z1c * HW + y0c * Wx;
    int zy11 = z1c * HW + y1c * Wx;

    int i000 = zy00 + x0c, i001 = zy00 + x1c;
    int i010 = zy01 + x0c, i011 = zy01 + x1c;
    int i100 = zy10 + x0c, i101 = zy10 + x1c;
    int i110 = zy11 + x0c, i111 = zy11 + x1c;

    float w000 = wz0 * wy0 * wx0, w001 = wz0 * wy0 * wx1;
    float w010 = wz0 * wy1 * wx0, w011 = wz0 * wy1 * wx1;
    float w100 = wz1 * wy0 * wx0, w101 = wz1 * wy0 * wx1;
    float w110 = wz1 * wy1 * wx0, w111 = wz1 * wy1 * wx1;

    const float* sb = src + (size_t)b * Cn * DHW;
    float* ob = out + (size_t)b * Cn * DHW;

    #pragma unroll
    for (int c = 0; c < Cn; c++) {
        const float* sc = sb + (size_t)c * DHW;
        float acc;
        acc  = w000 * __ldg(sc + i000);
        acc += w001 * __ldg(sc + i001);
        acc += w010 * __ldg(sc + i010);
        acc += w011 * __ldg(sc + i011);
        acc += w100 * __ldg(sc + i100);
        acc += w101 * __ldg(sc + i101);
        acc += w110 * __ldg(sc + i110);
        acc += w111 * __ldg(sc + i111);
        ob[(size_t)c * DHW + s] = acc;
    }
}

extern "C" void kernel_launch(void* const* d_in, const int* in_sizes, int n_in,
                              void* d_out, int out_size) {
    const float* src  = (const float*)d_in[0];
    const float* flow = (const float*)d_in[1];
    float* out = (float*)d_out;

    int total = Bn * DHW;
    int threads = 256;
    int blocks = (total + threads - 1) / threads;
    warp3d_kernel<<<blocks, threads>>>(src, flow, out);
}

// round 2
// speedup vs baseline: 1.0193x; 1.0193x over previous
#include <cuda_runtime.h>

// SpatialTransformer: out[b,c,d,h,w] = trilinear_sample(src[b,c], (w,h,d)+flow[b,:,d,h,w])
// align_corners=True normalization cancels; padding_mode='zeros'.
//
// Two-pass: (1) interleave channels into float2 scratch so each trilinear corner
// is one LDG.64 instead of two LDG.32 (halves L1 sector traffic, which R1 ncu
// showed to be the binding pipe at 83.9%), (2) gather.

#define Dz 160
#define Hy 192
#define Wx 160
#define Bn 2
#define Cn 2
#define HW (Hy * Wx)            // 30720
#define DHW (Dz * Hy * Wx)      // 4915200

// Channel-interleaved scratch: [b][dhw] -> (c0, c1). 2*4915200*8B = 78.6MB.
__device__ float2 g_ilv[Bn * DHW];

__global__ __launch_bounds__(256) void interleave_kernel(const float* __restrict__ src)
{
    // Each thread handles 4 consecutive voxels of one batch.
    int v = blockIdx.x * blockDim.x + threadIdx.x;
    int total = Bn * (DHW / 4);
    if (v >= total) return;
    int b = v / (DHW / 4);
    int g = v - b * (DHW / 4);      // float4 group within batch
    size_t base = (size_t)b * Cn * DHW + (size_t)g * 4;

    float4 a = *(const float4*)(src + base);            // channel 0
    float4 c = *(const float4*)(src + base + DHW);      // channel 1

    float4 o0 = make_float4(a.x, c.x, a.y, c.y);
    float4 o1 = make_float4(a.z, c.z, a.w, c.w);
    float4* dst = (float4*)(g_ilv + (size_t)b * DHW + (size_t)g * 4);
    dst[0] = o0;
    dst[1] = o1;
}

__global__ __launch_bounds__(256) void warp3d_kernel(
    const float* __restrict__ flow,
    float* __restrict__ out)
{
    int idx = blockIdx.x * blockDim.x + threadIdx.x;
    if (idx >= Bn * DHW) return;

    int b = idx / DHW;
    int s = idx - b * DHW;
    int w = s % Wx;
    int t = s / Wx;
    int h = t % Hy;
    int d = t / Hy;

    const float* fb = flow + (size_t)b * 3 * DHW;
    float x = (float)w + __ldg(fb + s);
    float y = (float)h + __ldg(fb + s + DHW);
    float z = (float)d + __ldg(fb + s + 2 * DHW);

    float x0f = floorf(x), y0f = floorf(y), z0f = floorf(z);
    float fx = x - x0f, fy = y - y0f, fz = z - z0f;
    int x0 = (int)x0f, y0 = (int)y0f, z0 = (int)z0f;
    int x1 = x0 + 1, y1 = y0 + 1, z1 = z0 + 1;

    // Per-axis weights, zeroed when that corner coordinate is out of bounds.
    float wx0 = (x0 >= 0 && x0 < Wx) ? (1.0f - fx) : 0.0f;
    float wx1 = (x1 >= 0 && x1 < Wx) ? fx          : 0.0f;
    float wy0 = (y0 >= 0 && y0 < Hy) ? (1.0f - fy) : 0.0f;
    float wy1 = (y1 >= 0 && y1 < Hy) ? fy          : 0.0f;
    float wz0 = (z0 >= 0 && z0 < Dz) ? (1.0f - fz) : 0.0f;
    float wz1 = (z1 >= 0 && z1 < Dz) ? fz          : 0.0f;

    // Clamped indices (safe even when weight is zero).
    int x0c = min(max(x0, 0), Wx - 1);
    int x1c = min(max(x1, 0), Wx - 1);
    int y0c = min(max(y0, 0), Hy - 1);
    int y1c = min(max(y1, 0), Hy - 1);
    int z0c = min(max(z0, 0), Dz - 1);
    int z1c = min(max(z1, 0), Dz - 1);

    const float2* sb = g_ilv + (size_t)b * DHW;

    int zy00 = z0c * HW + y0c * Wx;
    int zy01 = z0c * HW + y1c * Wx;
    int zy10 = z1c * HW + y0c * Wx;
    int zy11 = z1c * HW + y1c * Wx;

    float2 v000 = __ldg(sb + zy00 + x0c);
    float2 v001 = __ldg(sb + zy00 + x1c);
    float2 v010 = __ldg(sb + zy01 + x0c);
    float2 v011 = __ldg(sb + zy01 + x1c);
    float2 v100 = __ldg(sb + zy10 + x0c);
    float2 v101 = __ldg(sb + zy10 + x1c);
    float2 v110 = __ldg(sb + zy11 + x0c);
    float2 v111 = __ldg(sb + zy11 + x1c);

    float w000 = wz0 * wy0 * wx0, w001 = wz0 * wy0 * wx1;
    float w010 = wz0 * wy1 * wx0, w011 = wz0 * wy1 * wx1;
    float w100 = wz1 * wy0 * wx0, w101 = wz1 * wy0 * wx1;
    float w110 = wz1 * wy1 * wx0, w111 = wz1 * wy1 * wx1;

    float acc0, acc1;
    acc0  = w000 * v000.x;  acc1  = w000 * v000.y;
    acc0 += w001 * v001.x;  acc1 += w001 * v001.y;
    acc0 += w010 * v010.x;  acc1 += w010 * v010.y;
    acc0 += w011 * v011.x;  acc1 += w011 * v011.y;
    acc0 += w100 * v100.x;  acc1 += w100 * v100.y;
    acc0 += w101 * v101.x;  acc1 += w101 * v101.y;
    acc0 += w110 * v110.x;  acc1 += w110 * v110.y;
    acc0 += w111 * v111.x;  acc1 += w111 * v111.y;

    float* ob = out + (size_t)b * Cn * DHW;
    ob[s] = acc0;
    ob[DHW + s] = acc1;
}

extern "C" void kernel_launch(void* const* d_in, const int* in_sizes, int n_in,
                              void* d_out, int out_size) {
    const float* src  = (const float*)d_in[0];
    const float* flow = (const float*)d_in[1];
    float* out = (float*)d_out;

    int threads = 256;
    int total_t = Bn * (DHW / 4);
    interleave_kernel<<<(total_t + threads - 1) / threads, threads>>>(src);

    int total = Bn * DHW;
    warp3d_kernel<<<(total + threads - 1) / threads, threads>>>(flow, out);
}